// round 8
// baseline (speedup 1.0000x reference)
#include <cuda_runtime.h>
#include <cuda_fp16.h>

// M is [512, 65536] fp32. Sinkhorn; trip count in {1, 51, 100}; this input exits at 1.
// Fast path never materializes K; exp(-20M) is recomputed from M each pass. M is
// re-read with 256-bit evict_last loads (the only form ptxas accepts the hint on).
#define NR    512
#define NC    65536
#define GRID  128              // <= SM count: wave-1 co-residency guaranteed
#define TPB   512
#define CPB   512              // columns per block (full column stripe)

// Persistent scratch (__device__ globals per allocation rule)
__device__ __half   g_K[(size_t)NR * NC];       // fp16 K: built ONLY on the c>=2 fallback
__device__ float    g_sPart[2][GRID * NR];      // row partials of K.v   (parity-buffered)
__device__ float    g_qPart[2][GRID * NR];      // row partials of (K*M).v for the loss
__device__ float    g_errPart[GRID];
__device__ int      g_done;
__device__ unsigned g_bar = 0;
__device__ volatile unsigned g_gen = 0;         // monotone across graph replays

// 256-bit L2-evict-last load (sm_103a: hint requires .v8.b32). 32B-aligned addr.
__device__ __forceinline__ void ldg_el8(const float* p, float4 &a, float4 &b) {
    asm volatile("ld.global.nc.L2::evict_last.v8.b32 {%0,%1,%2,%3,%4,%5,%6,%7}, [%8];"
                 : "=f"(a.x), "=f"(a.y), "=f"(a.z), "=f"(a.w),
                   "=f"(b.x), "=f"(b.y), "=f"(b.z), "=f"(b.w)
                 : "l"(p));
}

// Grid barrier: GRID <= #SMs -> cannot deadlock. Spin cap = escape hatch only.
__device__ __forceinline__ void gsync(unsigned &phase) {
    __syncthreads();
    if (threadIdx.x == 0) {
        ++phase;
        __threadfence();
        if (atomicAdd(&g_bar, 1u) == GRID - 1u) {
            g_bar = 0u;
            __threadfence();
            g_gen = phase;
        } else {
            unsigned spins = 0;
            while (g_gen < phase) {
                __nanosleep(64);
                if (++spins > (1u << 18)) break;
            }
        }
    }
    __syncthreads();
}

__device__ __forceinline__ float blockReduce512(float x, float* sh) {
    const int t = threadIdx.x;
    sh[t] = x; __syncthreads();
    if (t < 256) sh[t] += sh[t + 256];
    __syncthreads();
    if (t < 128) sh[t] += sh[t + 128];
    __syncthreads();
    if (t < 64)  sh[t] += sh[t + 64];
    __syncthreads();
    if (t < 32) {
        float v = sh[t] + sh[t + 32];
        #pragma unroll
        for (int o = 16; o; o >>= 1) v += __shfl_down_sync(0xffffffffu, v, o);
        if (t == 0) sh[0] = v;
    }
    __syncthreads();
    float r = sh[0];
    __syncthreads();
    return r;
}

__global__ void __launch_bounds__(TPB, 1)
sinkhorn_all(const float* __restrict__ M, float* __restrict__ out) {
    __shared__ float sh[TPB];
    __shared__ float sh_u[NR];
    __shared__ float sh_v[CPB];
    const int tid = threadIdx.x;
    const int bid = blockIdx.x;
    unsigned phase = g_gen;                   // continue barrier generation across replays

    const int    j  = bid * CPB + tid;        // owned column
    const float* Mj = M + j;
    const int    w    = tid >> 5;
    const int    lane = tid & 31;

    float v;                                  // v_j of current iteration
    float lossLoc = 0.0f;                     // full loss, replicated per block

    // ===== pass 1 (c=1 phase A): t_j = (1/NR) * sum_i exp(-20 M_ij) =====
    {
        float t0 = 0.0f, t1 = 0.0f;
        #pragma unroll 8
        for (int r = 0; r < NR; r += 2) {
            float m0 = __ldg(&Mj[(size_t)r * NC]);
            float m1 = __ldg(&Mj[(size_t)(r + 1) * NC]);
            t0 += __expf(-20.0f * m0);
            t1 += __expf(-20.0f * m1);
        }
        v = (1.0f / NC) / ((t0 + t1) * (1.0f / NR) + 1e-16f);
    }

    // ---- phase C over M (fast path): per-row partials of K.v AND (K*M).v via
    // 256-bit evict_last loads. One gsync; each block reduces full u+loss locally.
    #define PHASE_C_M(par)                                                         \
    {                                                                              \
        sh_v[tid] = v; __syncthreads();                                            \
        _Pragma("unroll 2")                                                        \
        for (int rr = 0; rr < 32; ++rr) {                                          \
            const int row = w * 32 + rr;                                           \
            const float* mrow = M + (size_t)row * NC + bid * CPB;                  \
            const float4* v4  = (const float4*)sh_v;                               \
            float s = 0.0f, q = 0.0f;                                              \
            _Pragma("unroll")                                                      \
            for (int c = lane; c < 64; c += 32) {                                  \
                float4 ma, mb;                                                     \
                ldg_el8(mrow + c * 8, ma, mb);                                     \
                float4 va = v4[2 * c], vb = v4[2 * c + 1];                         \
                float k0 = __expf(-20.0f * ma.x);                                  \
                float k1 = __expf(-20.0f * ma.y);                                  \
                float k2 = __expf(-20.0f * ma.z);                                  \
                float k3 = __expf(-20.0f * ma.w);                                  \
                s = fmaf(k0, va.x, s); q = fmaf(k0 * ma.x, va.x, q);               \
                s = fmaf(k1, va.y, s); q = fmaf(k1 * ma.y, va.y, q);               \
                s = fmaf(k2, va.z, s); q = fmaf(k2 * ma.z, va.z, q);               \
                s = fmaf(k3, va.w, s); q = fmaf(k3 * ma.w, va.w, q);               \
                float k4 = __expf(-20.0f * mb.x);                                  \
                float k5 = __expf(-20.0f * mb.y);                                  \
                float k6 = __expf(-20.0f * mb.z);                                  \
                float k7 = __expf(-20.0f * mb.w);                                  \
                s = fmaf(k4, vb.x, s); q = fmaf(k4 * mb.x, vb.x, q);               \
                s = fmaf(k5, vb.y, s); q = fmaf(k5 * mb.y, vb.y, q);               \
                s = fmaf(k6, vb.z, s); q = fmaf(k6 * mb.z, vb.z, q);               \
                s = fmaf(k7, vb.w, s); q = fmaf(k7 * mb.w, vb.w, q);               \
            }                                                                      \
            _Pragma("unroll")                                                      \
            for (int o = 16; o; o >>= 1) {                                         \
                s += __shfl_down_sync(0xffffffffu, s, o);                          \
                q += __shfl_down_sync(0xffffffffu, q, o);                          \
            }                                                                      \
            if (lane == 0) {                                                       \
                g_sPart[par][bid * NR + row] = s;                                  \
                g_qPart[par][bid * NR + row] = q;                                  \
            }                                                                      \
        }                                                                          \
        gsync(phase);                                                              \
        {                                                                          \
            float su = 0.0f, qu = 0.0f;                                            \
            _Pragma("unroll 8")                                                    \
            for (int b = 0; b < GRID; ++b) {                                       \
                su += __ldcg(&g_sPart[par][b * NR + tid]);                         \
                qu += __ldcg(&g_qPart[par][b * NR + tid]);                         \
            }                                                                      \
            float u = (1.0f / NR) / (su + 1e-16f);                                 \
            sh_u[tid] = u;                                                         \
            lossLoc = blockReduce512(u * qu, sh);                                  \
        }                                                                          \
    }

    // ---- phase C over fp16 K (fallback, non-exit iterations; no loss needed) ----
    #define PHASE_C_K(par)                                                         \
    {                                                                              \
        sh_v[tid] = v; __syncthreads();                                            \
        _Pragma("unroll 2")                                                        \
        for (int rr = 0; rr < 32; ++rr) {                                          \
            const int row = w * 32 + rr;                                           \
            const uint4* kp = (const uint4*)(g_K + (size_t)row * NC + bid * CPB);  \
            const float4* v4 = (const float4*)sh_v;                                \
            float s = 0.0f;                                                        \
            _Pragma("unroll")                                                      \
            for (int c = lane; c < 64; c += 32) {                                  \
                uint4 kk = kp[c];                                                  \
                const __half2* kh = (const __half2*)&kk;                           \
                float4 va = v4[2 * c], vb = v4[2 * c + 1];                         \
                float2 k0 = __half22float2(kh[0]);                                 \
                float2 k1 = __half22float2(kh[1]);                                 \
                float2 k2 = __half22float2(kh[2]);                                 \
                float2 k3 = __half22float2(kh[3]);                                 \
                s = fmaf(k0.x, va.x, s); s = fmaf(k0.y, va.y, s);                  \
                s = fmaf(k1.x, va.z, s); s = fmaf(k1.y, va.w, s);                  \
                s = fmaf(k2.x, vb.x, s); s = fmaf(k2.y, vb.y, s);                  \
                s = fmaf(k3.x, vb.z, s); s = fmaf(k3.y, vb.w, s);                  \
            }                                                                      \
            _Pragma("unroll")                                                      \
            for (int o = 16; o; o >>= 1) s += __shfl_down_sync(0xffffffffu, s, o); \
            if (lane == 0) g_sPart[par][bid * NR + row] = s;                       \
        }                                                                          \
        gsync(phase);                                                              \
        {                                                                          \
            float su = 0.0f;                                                       \
            _Pragma("unroll 8")                                                    \
            for (int b = 0; b < GRID; ++b)                                         \
                su += __ldcg(&g_sPart[par][b * NR + tid]);                         \
            sh_u[tid] = (1.0f / NR) / (su + 1e-16f);                               \
            __syncthreads();                                                       \
        }                                                                          \
    }

    // ---- err pass (fp32, lean): tp = K^T u; err = sum|v*tp - b|. On converged,
    // block 0 writes out = 100 * lossLoc (already reduced). Else v <- b/(tp+eps).
    #define ERR_CHECK(done_var)                                                    \
    {                                                                              \
        float a0 = 0.0f, a1 = 0.0f, a2 = 0.0f, a3 = 0.0f;                          \
        _Pragma("unroll 4")                                                        \
        for (int r = 0; r < NR; r += 4) {                                          \
            float m0 = __ldg(&Mj[(size_t)(r + 0) * NC]);                           \
            float m1 = __ldg(&Mj[(size_t)(r + 1) * NC]);                           \
            float m2 = __ldg(&Mj[(size_t)(r + 2) * NC]);                           \
            float m3 = __ldg(&Mj[(size_t)(r + 3) * NC]);                           \
            a0 = fmaf(__expf(-20.0f * m0), sh_u[r + 0], a0);                       \
            a1 = fmaf(__expf(-20.0f * m1), sh_u[r + 1], a1);                       \
            a2 = fmaf(__expf(-20.0f * m2), sh_u[r + 2], a2);                       \
            a3 = fmaf(__expf(-20.0f * m3), sh_u[r + 3], a3);                       \
        }                                                                          \
        float tp = (a0 + a1) + (a2 + a3);                                          \
        float eb = blockReduce512(fabsf(v * tp - (1.0f / NC)), sh);                \
        if (tid == 0) g_errPart[bid] = eb;                                         \
        float vn = (1.0f / NC) / (tp + 1e-16f);                                    \
        gsync(phase);                                                              \
        if (bid == 0) {                                                            \
            float ep = (tid < GRID) ? __ldcg(&g_errPart[tid]) : 0.0f;              \
            float et = blockReduce512(ep, sh);                                     \
            int dn = (et <= 0.005f);                                               \
            if (tid == 0) {                                                        \
                if (dn) out[0] = 100.0f * lossLoc;                                 \
                g_done = dn;                                                       \
            }                                                                      \
        }                                                                          \
        gsync(phase);                                                              \
        v = vn;                                                                    \
        done_var = __ldcg(&g_done);                                                \
    }

    // ===== c = 1: phase C -> u_1 (+loss); err check (3 gsyncs on fast path) =====
    PHASE_C_M(0);
    int done;
    ERR_CHECK(done);
    if (done) return;                         // trip-1 fast path ends here

    // ===== fallback (c >= 2): build fp16 K once, then iterate =====
    {
        __half* Kj = g_K + j;
        #pragma unroll 8
        for (int r = 0; r < NR; ++r)
            Kj[(size_t)r * NC] = __float2half(__expf(-20.0f * __ldg(&Mj[(size_t)r * NC])));
        __syncthreads();                      // K stripe is block-local
    }

    for (int c = 2; c <= 100; ++c) {
        if (c > 2 && c != 52) {
            // phase A: t_j = sum_i K_ij u_i (fp16 K, own column); v_j = b/(t+eps)
            float t = 0.0f;
            const __half* kc = g_K + j;
            #pragma unroll 16
            for (int r = 0; r < NR; ++r)
                t = fmaf(__half2float(kc[(size_t)r * NC]), sh_u[r], t);
            v = (1.0f / NC) / (t + 1e-16f);
        } // c==2 / c==52: v already produced in fp32 by ERR_CHECK

        if (c == 51 || c == 100) {
            PHASE_C_M(c & 1);                 // exit candidates need loss (q) too
        } else {
            PHASE_C_K(c & 1);
        }

        if (c == 51) {
            ERR_CHECK(done);
            if (done) return;
        }
    }

    // ===== cap exit (cpt=100): loss already reduced by PHASE_C_M(100) =====
    if (bid == 0 && tid == 0) out[0] = 100.0f * lossLoc;
}

extern "C" void kernel_launch(void* const* d_in, const int* in_sizes, int n_in,
                              void* d_out, int out_size) {
    const float* M = (const float*)d_in[0];
    float* out = (float*)d_out;
    sinkhorn_all<<<GRID, TPB>>>(M, out);
}